// round 1
// baseline (speedup 1.0000x reference)
#include <cuda_runtime.h>

#define NV 4096            // nodes per graph
#define NB 32              // batch size (== warp size, load-bearing)
#define BN (NV * NB)       // 131072
#define CAP 256            // ELL row capacity (mean degree 128, +11 sigma headroom)

// ---- scratch (device globals; no allocation allowed) ----
__device__ float  g_xt  [BN];        // x,  node-major [node][batch]
__device__ float  g_fxt [BN];        // tanh(x), node-major
__device__ float  g_mut [BN];        // mu, node-major
__device__ float  g_epst[BN];        // eps = x - mu, node-major
__device__ float  g_dxt [BN];        // dx, node-major
__device__ int    g_cnt_dst[NV];
__device__ int    g_cnt_src[NV];
__device__ float2 g_ellF[NV * CAP];  // rows keyed by dst: (src, w)
__device__ float2 g_ellB[NV * CAP];  // rows keyed by src: (dst, w)

// Transpose x [B,N] -> node-major, apply tanh, zero counters.
// CTA = 1024 threads = 32x32 tile over (batch, 32 nodes). grid = NV/32 = 128.
__global__ void k_prep(const float* __restrict__ x) {
    __shared__ float s[32][33];
    int tx = threadIdx.x & 31;
    int ty = threadIdx.x >> 5;
    int i0 = blockIdx.x * 32;

    // read batch-major: batch=ty, node=i0+tx  (coalesced)
    s[ty][tx] = x[ty * NV + i0 + tx];
    __syncthreads();

    // write node-major: node=i0+ty, batch=tx  (coalesced)
    float xv = s[tx][ty];
    int o = (i0 + ty) * NB + tx;
    g_xt[o]  = xv;
    g_fxt[o] = tanhf(xv);

    int gid = blockIdx.x * 1024 + threadIdx.x;
    if (gid < NV) { g_cnt_dst[gid] = 0; g_cnt_src[gid] = 0; }
}

// Build both ELL adjacency structures.
__global__ void k_build(const float* __restrict__ w,
                        const int* __restrict__ esrc,
                        const int* __restrict__ edst, int E) {
    int e = blockIdx.x * blockDim.x + threadIdx.x;
    if (e >= E) return;
    int   s  = esrc[e];
    int   d  = edst[e];
    float wt = w[e];

    int p = atomicAdd(&g_cnt_dst[d], 1);
    if (p < CAP) g_ellF[(d << 8) + p] = make_float2(__int_as_float(s), wt);
    int q = atomicAdd(&g_cnt_src[s], 1);
    if (q < CAP) g_ellB[(s << 8) + q] = make_float2(__int_as_float(d), wt);
}

// Forward SpMM: mu[node][b] = sum_{e: dst=node} w_e * fx[src_e][b]; also eps.
// One warp per node, lane = batch.
__global__ void k_mu() {
    int node = (blockIdx.x * blockDim.x + threadIdx.x) >> 5;
    int lane = threadIdx.x & 31;
    if (node >= NV) return;

    int n = min(g_cnt_dst[node], CAP);
    const float2* __restrict__ row = g_ellF + (node << 8);

    float a0 = 0.f, a1 = 0.f, a2 = 0.f, a3 = 0.f;
    int j = 0;
    for (; j + 4 <= n; j += 4) {
        float2 e0 = row[j + 0];
        float2 e1 = row[j + 1];
        float2 e2 = row[j + 2];
        float2 e3 = row[j + 3];
        a0 = fmaf(e0.y, g_fxt[(__float_as_int(e0.x) << 5) + lane], a0);
        a1 = fmaf(e1.y, g_fxt[(__float_as_int(e1.x) << 5) + lane], a1);
        a2 = fmaf(e2.y, g_fxt[(__float_as_int(e2.x) << 5) + lane], a2);
        a3 = fmaf(e3.y, g_fxt[(__float_as_int(e3.x) << 5) + lane], a3);
    }
    for (; j < n; j++) {
        float2 e0 = row[j];
        a0 = fmaf(e0.y, g_fxt[(__float_as_int(e0.x) << 5) + lane], a0);
    }
    float mu = (a0 + a1) + (a2 + a3);
    int o = (node << 5) + lane;
    g_mut[o]  = mu;
    g_epst[o] = g_xt[o] - mu;
}

// Backward SpMM: acc[node][b] = sum_{e: src=node} w_e * eps[dst_e][b];
// dx = -eps + (1 - fx^2) * acc.
__global__ void k_dx() {
    int node = (blockIdx.x * blockDim.x + threadIdx.x) >> 5;
    int lane = threadIdx.x & 31;
    if (node >= NV) return;

    int n = min(g_cnt_src[node], CAP);
    const float2* __restrict__ row = g_ellB + (node << 8);

    float a0 = 0.f, a1 = 0.f, a2 = 0.f, a3 = 0.f;
    int j = 0;
    for (; j + 4 <= n; j += 4) {
        float2 e0 = row[j + 0];
        float2 e1 = row[j + 1];
        float2 e2 = row[j + 2];
        float2 e3 = row[j + 3];
        a0 = fmaf(e0.y, g_epst[(__float_as_int(e0.x) << 5) + lane], a0);
        a1 = fmaf(e1.y, g_epst[(__float_as_int(e1.x) << 5) + lane], a1);
        a2 = fmaf(e2.y, g_epst[(__float_as_int(e2.x) << 5) + lane], a2);
        a3 = fmaf(e3.y, g_epst[(__float_as_int(e3.x) << 5) + lane], a3);
    }
    for (; j < n; j++) {
        float2 e0 = row[j];
        a0 = fmaf(e0.y, g_epst[(__float_as_int(e0.x) << 5) + lane], a0);
    }
    float acc = (a0 + a1) + (a2 + a3);
    int o = (node << 5) + lane;
    float eps = g_epst[o];
    float fx  = g_fxt[o];
    g_dxt[o] = fmaf(fmaf(-fx, fx, 1.0f), acc, -eps);
}

// Transpose node-major mu/dx back to batch-major output [2, B*N].
// grid = 256: blocks 0..127 -> mu, 128..255 -> dx. CTA = 1024 (32x32 tile).
__global__ void k_out(float* __restrict__ out) {
    __shared__ float s[32][33];
    int which = blockIdx.x >> 7;
    int t0    = (blockIdx.x & 127) * 32;
    const float* __restrict__ srcT = which ? g_dxt : g_mut;

    int tx = threadIdx.x & 31;
    int ty = threadIdx.x >> 5;

    // read node-major: node=t0+ty, batch=tx (coalesced)
    s[ty][tx] = srcT[(t0 + ty) * NB + tx];
    __syncthreads();

    // write batch-major: batch=ty, node=t0+tx (coalesced)
    out[which * BN + ty * NV + t0 + tx] = s[tx][ty];
}

extern "C" void kernel_launch(void* const* d_in, const int* in_sizes, int n_in,
                              void* d_out, int out_size) {
    const float* x    = (const float*)d_in[0];
    const float* w    = (const float*)d_in[1];
    const int*   esrc = (const int*)d_in[2];
    const int*   edst = (const int*)d_in[3];
    float*       out  = (float*)d_out;
    int E = in_sizes[1];

    k_prep <<<NV / 32, 1024>>>(x);
    k_build<<<(E + 255) / 256, 256>>>(w, esrc, edst, E);
    k_mu   <<<NV * 32 / 256, 256>>>();
    k_dx   <<<NV * 32 / 256, 256>>>();
    k_out  <<<256, 1024>>>(out);
}

// round 2
// speedup vs baseline: 1.4134x; 1.4134x over previous
#include <cuda_runtime.h>

#define NV 4096            // nodes per graph
#define NB 32              // batch size (== warp size, load-bearing)
#define BN (NV * NB)       // 131072
#define CAP 256            // ELL row capacity (mean degree 128, +11 sigma headroom)

// ---- scratch (device globals; no allocation allowed) ----
__device__ float  g_xt  [BN];        // x,  node-major [node][batch]
__device__ float  g_fxt [BN];        // tanh(x), node-major
__device__ float  g_mut [BN];        // mu, node-major
__device__ float  g_epst[BN];        // eps = x - mu, node-major
__device__ float  g_dxt [BN];        // dx, node-major
__device__ int    g_cnt_dst[NV];
__device__ int    g_cnt_src[NV];
__device__ float2 g_ellF[NV * CAP];  // rows keyed by dst: (src, w)
__device__ float2 g_ellB[NV * CAP];  // rows keyed by src: (dst, w)

// Transpose x [B,N] -> node-major, apply tanh, zero counters.
// CTA = 1024 threads = 32x32 tile. grid = NV/32 = 128.
__global__ void k_prep(const float* __restrict__ x) {
    __shared__ float s[32][33];
    int tx = threadIdx.x & 31;
    int ty = threadIdx.x >> 5;
    int i0 = blockIdx.x * 32;

    s[ty][tx] = x[ty * NV + i0 + tx];          // batch-major read (coalesced)
    __syncthreads();

    float xv = s[tx][ty];
    int o = (i0 + ty) * NB + tx;               // node-major write (coalesced)
    g_xt[o]  = xv;
    g_fxt[o] = tanhf(xv);

    int gid = blockIdx.x * 1024 + threadIdx.x;
    if (gid < NV) { g_cnt_dst[gid] = 0; g_cnt_src[gid] = 0; }
}

// Build both ELL adjacency structures.
__global__ void k_build(const float* __restrict__ w,
                        const int* __restrict__ esrc,
                        const int* __restrict__ edst, int E) {
    int e = blockIdx.x * blockDim.x + threadIdx.x;
    if (e >= E) return;
    int   s  = esrc[e];
    int   d  = edst[e];
    float wt = w[e];

    int p = atomicAdd(&g_cnt_dst[d], 1);
    if (p < CAP) g_ellF[(d << 8) + p] = make_float2(__int_as_float(s), wt);
    int q = atomicAdd(&g_cnt_src[s], 1);
    if (q < CAP) g_ellB[(s << 8) + q] = make_float2(__int_as_float(d), wt);
}

// Warp-level SpMM slice: accumulate sum over row[jb..je) of w_e * tab[col_e][lane].
// Unroll-8 for 8 independent gathers in flight; 4 accumulators.
__device__ __forceinline__ float spmm_slice(const float2* __restrict__ row,
                                            const float* __restrict__ tab,
                                            int jb, int je, int lane) {
    float a0 = 0.f, a1 = 0.f, a2 = 0.f, a3 = 0.f;
    int j = jb;
    for (; j + 8 <= je; j += 8) {
        float2 e0 = row[j + 0]; float2 e1 = row[j + 1];
        float2 e2 = row[j + 2]; float2 e3 = row[j + 3];
        float2 e4 = row[j + 4]; float2 e5 = row[j + 5];
        float2 e6 = row[j + 6]; float2 e7 = row[j + 7];
        float v0 = tab[(__float_as_int(e0.x) << 5) + lane];
        float v1 = tab[(__float_as_int(e1.x) << 5) + lane];
        float v2 = tab[(__float_as_int(e2.x) << 5) + lane];
        float v3 = tab[(__float_as_int(e3.x) << 5) + lane];
        float v4 = tab[(__float_as_int(e4.x) << 5) + lane];
        float v5 = tab[(__float_as_int(e5.x) << 5) + lane];
        float v6 = tab[(__float_as_int(e6.x) << 5) + lane];
        float v7 = tab[(__float_as_int(e7.x) << 5) + lane];
        a0 = fmaf(e0.y, v0, a0); a1 = fmaf(e1.y, v1, a1);
        a2 = fmaf(e2.y, v2, a2); a3 = fmaf(e3.y, v3, a3);
        a0 = fmaf(e4.y, v4, a0); a1 = fmaf(e5.y, v5, a1);
        a2 = fmaf(e6.y, v6, a2); a3 = fmaf(e7.y, v7, a3);
    }
    for (; j < je; j++) {
        float2 e0 = row[j];
        a0 = fmaf(e0.y, tab[(__float_as_int(e0.x) << 5) + lane], a0);
    }
    return (a0 + a1) + (a2 + a3);
}

// Forward SpMM: mu[node][b] = sum_{e: dst=node} w_e * fx[src_e][b]; also eps.
// 4 warps per node (quarter rows), smem partial reduction.
// block = 256 = 2 nodes x 4 warps; grid = NV/2 = 2048.
__global__ void k_mu() {
    __shared__ float part[2][4][32];
    int warp  = threadIdx.x >> 5;
    int lane  = threadIdx.x & 31;
    int local = warp >> 2;                 // 0..1
    int q     = warp & 3;                  // 0..3
    int node  = (blockIdx.x << 1) + local;

    int n  = min(g_cnt_dst[node], CAP);
    int jb = (n * q) >> 2;
    int je = (n * (q + 1)) >> 2;
    const float2* __restrict__ row = g_ellF + (node << 8);

    part[local][q][lane] = spmm_slice(row, g_fxt, jb, je, lane);
    __syncthreads();

    if (q == 0) {
        float mu = (part[local][0][lane] + part[local][1][lane])
                 + (part[local][2][lane] + part[local][3][lane]);
        int o = (node << 5) + lane;
        g_mut[o]  = mu;
        g_epst[o] = g_xt[o] - mu;
    }
}

// Backward SpMM: acc[node][b] = sum_{e: src=node} w_e * eps[dst_e][b];
// dx = -eps + (1 - fx^2) * acc.
__global__ void k_dx() {
    __shared__ float part[2][4][32];
    int warp  = threadIdx.x >> 5;
    int lane  = threadIdx.x & 31;
    int local = warp >> 2;
    int q     = warp & 3;
    int node  = (blockIdx.x << 1) + local;

    int n  = min(g_cnt_src[node], CAP);
    int jb = (n * q) >> 2;
    int je = (n * (q + 1)) >> 2;
    const float2* __restrict__ row = g_ellB + (node << 8);

    part[local][q][lane] = spmm_slice(row, g_epst, jb, je, lane);
    __syncthreads();

    if (q == 0) {
        float acc = (part[local][0][lane] + part[local][1][lane])
                  + (part[local][2][lane] + part[local][3][lane]);
        int o = (node << 5) + lane;
        float eps = g_epst[o];
        float fx  = g_fxt[o];
        g_dxt[o] = fmaf(fmaf(-fx, fx, 1.0f), acc, -eps);
    }
}

// Transpose node-major mu/dx back to batch-major output [2, B*N].
// grid = 256: blocks 0..127 -> mu, 128..255 -> dx. CTA = 1024 (32x32 tile).
__global__ void k_out(float* __restrict__ out) {
    __shared__ float s[32][33];
    int which = blockIdx.x >> 7;
    int t0    = (blockIdx.x & 127) * 32;
    const float* __restrict__ srcT = which ? g_dxt : g_mut;

    int tx = threadIdx.x & 31;
    int ty = threadIdx.x >> 5;

    s[ty][tx] = srcT[(t0 + ty) * NB + tx];     // node-major read (coalesced)
    __syncthreads();

    out[which * BN + ty * NV + t0 + tx] = s[tx][ty];  // batch-major write (coalesced)
}

extern "C" void kernel_launch(void* const* d_in, const int* in_sizes, int n_in,
                              void* d_out, int out_size) {
    const float* x    = (const float*)d_in[0];
    const float* w    = (const float*)d_in[1];
    const int*   esrc = (const int*)d_in[2];
    const int*   edst = (const int*)d_in[3];
    float*       out  = (float*)d_out;
    int E = in_sizes[1];

    k_prep <<<NV / 32, 1024>>>(x);
    k_build<<<(E + 255) / 256, 256>>>(w, esrc, edst, E);
    k_mu   <<<NV / 2, 256>>>();
    k_dx   <<<NV / 2, 256>>>();
    k_out  <<<256, 1024>>>(out);
}